// round 13
// baseline (speedup 1.0000x reference)
#include <cuda_runtime.h>
#include <cuda_fp16.h>
#include <cstdint>

#define BATCH 512
#define IDIM 256
#define ODIM 256
#define CDIM 128
#define HDIM 128
#define IO (IDIM * ODIM)        // 65536
#define W2COLS (IO + ODIM)      // 65792
#define KTOT (HDIM * IDIM)      // 32768
#define KE 384                  // extended K: 256 (x/base) + 128 (h/biascols)
#define NSLICES 37              // 36 x (14 main BK) + 1 x (8 main + 6 ext BK)
#define BM 256
#define BN 128
#define BK 64
#define NST 14                  // stages per slice (uniform)

// ------------------------- device scratch (no allocs) -----------------------
__device__ __half g_X[(size_t)BATCH * IDIM];                // 256 KB, [b][i]
__device__ __half g_H[(size_t)129 * BATCH];                 // [hh][b]; row 128 = 1.0
__device__ __half g_Zext[(size_t)BATCH * KE];
__device__ float g_part[(size_t)NSLICES * BATCH * ODIM];

// ------------------------- PTX helpers --------------------------------------
__device__ __forceinline__ uint32_t smem_u32(const void* p) {
    uint32_t a;
    asm("{ .reg .u64 t; cvta.to.shared.u64 t, %1; cvt.u32.u64 %0, t; }"
        : "=r"(a) : "l"(p));
    return a;
}
__device__ __forceinline__ void cp16(uint32_t s, const void* g) {
    asm volatile("cp.async.cg.shared.global [%0], [%1], 16;" :: "r"(s), "l"(g));
}
#define CP_COMMIT() asm volatile("cp.async.commit_group;" ::: "memory")
#define CP_WAIT(n)  asm volatile("cp.async.wait_group %0;" :: "n"(n) : "memory")

#define LDSM4(r0, r1, r2, r3, addr) \
    asm volatile("ldmatrix.sync.aligned.m8n8.x4.shared.b16 {%0,%1,%2,%3}, [%4];" \
        : "=r"(r0), "=r"(r1), "=r"(r2), "=r"(r3) : "r"(addr))

#define LDSM4T(r0, r1, r2, r3, addr) \
    asm volatile("ldmatrix.sync.aligned.m8n8.x4.trans.shared.b16 {%0,%1,%2,%3}, [%4];" \
        : "=r"(r0), "=r"(r1), "=r"(r2), "=r"(r3) : "r"(addr))

#define MMA16816(c, a, b0, b1) \
    asm volatile("mma.sync.aligned.m16n8k16.row.col.f32.f16.f16.f32 " \
        "{%0,%1,%2,%3}, {%4,%5,%6,%7}, {%8,%9}, {%0,%1,%2,%3};" \
        : "+f"((c)[0]), "+f"((c)[1]), "+f"((c)[2]), "+f"((c)[3]) \
        : "r"((a)[0]), "r"((a)[1]), "r"((a)[2]), "r"((a)[3]), "r"(b0), "r"(b1))

#define HMUL2(d, s) asm volatile("mul.f16x2 %0, %0, %1;" : "+r"(d) : "r"(s))

__device__ __forceinline__ uint32_t pack_h2(float lo, float hi) {
    __half2 h = __float22half2_rn(make_float2(lo, hi));
    return *(uint32_t*)&h;
}

// ------------------------- prep kernel (tiny) --------------------------------
// one block per batch row: h, g_X row, g_H col, Zext
__global__ void __launch_bounds__(256)
prep_kernel(const float* __restrict__ x,
            const float* __restrict__ cond,
            const float* __restrict__ w1,
            const float* __restrict__ b1) {
    __shared__ float cs[CDIM];
    __shared__ float xs[IDIM];
    const int b = blockIdx.x;
    const int tid = threadIdx.x;
    if (tid < CDIM) cs[tid] = cond[b * CDIM + tid];
    xs[tid] = x[b * IDIM + tid];
    __syncthreads();
    __half xh = __float2half_rn(xs[tid]);
    g_X[b * IDIM + tid] = xh;
    g_Zext[b * KE + tid] = xh;
    if (tid < HDIM) {
        float a0 = b1[tid], a1 = 0.f, a2 = 0.f, a3 = 0.f;
#pragma unroll 8
        for (int k = 0; k < CDIM; k += 4) {
            a0 = fmaf(cs[k],     w1[(k)     * HDIM + tid], a0);
            a1 = fmaf(cs[k + 1], w1[(k + 1) * HDIM + tid], a1);
            a2 = fmaf(cs[k + 2], w1[(k + 2) * HDIM + tid], a2);
            a3 = fmaf(cs[k + 3], w1[(k + 3) * HDIM + tid], a3);
        }
        __half hv = __float2half_rn(fmaxf((a0 + a1) + (a2 + a3), 0.0f));
        g_H[tid * BATCH + b] = hv;              // [hh][b]
        g_Zext[b * KE + 256 + tid] = hv;
    }
    if (tid == 255) g_H[128 * BATCH + b] = __float2half_rn(1.0f);
}

// ------------------------- HMMA GEMM (A on-the-fly, B converted inline) -----
// C = (h∘x)@W (+ ext). A-tile = x fp16 tile scaled by per-stage h in regs.
// B-tile read DIRECTLY from fp32 w2/baseW/b2 via LDG, cvt to fp16, STS into
// swizzled smem. BM=256 x BN=128, 256 threads (8 warps, 4m x 2n, warp 64x64),
// BK=64, 4-stage pipeline. grid 2x2x37 = 148 CTAs = one per SM.
#define STG_BYTES 49664          // A 32K + B 16K + h 512 + pad
#define OFF_A 0
#define OFF_B 32768
#define OFF_H 49152
#define SMEM_TOTAL (4 * STG_BYTES)   // 198656

__global__ void __launch_bounds__(256, 1)
gemm_hmma_kernel(const float* __restrict__ w2,
                 const float* __restrict__ baseW,
                 const float* __restrict__ b2) {
    extern __shared__ char smem[];
    const uint32_t sbase = smem_u32(smem);
    const int tid = threadIdx.x;
    const int wid = tid >> 5, lane = tid & 31;
    const int n0 = blockIdx.x * BN;
    const int m0 = blockIdx.y * BM;
    const int z = blockIdx.z;
    const bool mixed = (z == NSLICES - 1);

    const int m_base = (wid >> 1) * 64;   // 4 warps along M
    const int n_base = (wid & 1) * 64;    // 2 warps along N

    // B load geometry: row = (tid>>4) + 16*i (i<4), col chunk = tid&15 (8 fp32)
    const int brow0 = tid >> 4;
    const int bcol = tid & 15;

    auto ldgB = [&](int kt, float4 (&Bv)[4][2]) {
        if (!mixed || kt < 8) {
            int k0 = (z * NST + kt) * BK;
            int hh = k0 >> 8, i0 = k0 & 255;
            const float* src = w2 + (size_t)hh * W2COLS + (size_t)i0 * 256
                               + n0 + bcol * 8;
#pragma unroll
            for (int i = 0; i < 4; i++) {
                const float* p = src + (size_t)(brow0 + i * 16) * 256;
                Bv[i][0] = *(const float4*)p;
                Bv[i][1] = *(const float4*)(p + 4);
            }
        } else {
            int kb = (kt - 8) * BK;
#pragma unroll
            for (int i = 0; i < 4; i++) {
                int r = kb + brow0 + i * 16;
                if (r < 256) {
                    const float* pa = baseW + (size_t)r * 256 + n0 + bcol * 8;
                    const float* pc = b2 + (size_t)r * 256 + n0 + bcol * 8;
                    float4 a0 = *(const float4*)pa, a1 = *(const float4*)(pa + 4);
                    float4 c0 = *(const float4*)pc, c1 = *(const float4*)(pc + 4);
                    Bv[i][0] = make_float4(a0.x + c0.x, a0.y + c0.y,
                                           a0.z + c0.z, a0.w + c0.w);
                    Bv[i][1] = make_float4(a1.x + c1.x, a1.y + c1.y,
                                           a1.z + c1.z, a1.w + c1.w);
                } else {
                    const float* p = w2 + (size_t)(r - 256) * W2COLS + IO
                                     + n0 + bcol * 8;
                    Bv[i][0] = *(const float4*)p;
                    Bv[i][1] = *(const float4*)(p + 4);
                }
            }
        }
    };

    auto stsB = [&](int kt, const float4 (&Bv)[4][2]) {
        uint32_t sb = sbase + (uint32_t)(kt & 3) * STG_BYTES;
#pragma unroll
        for (int i = 0; i < 4; i++) {
            int row = brow0 + i * 16;
            uint32_t sw = sb + OFF_B + (uint32_t)row * 256
                          + (((uint32_t)bcol ^ (row & 7)) << 4);
            uint32_t u0 = pack_h2(Bv[i][0].x, Bv[i][0].y);
            uint32_t u1 = pack_h2(Bv[i][0].z, Bv[i][0].w);
            uint32_t u2 = pack_h2(Bv[i][1].x, Bv[i][1].y);
            uint32_t u3 = pack_h2(Bv[i][1].z, Bv[i][1].w);
            asm volatile("st.shared.v4.b32 [%0], {%1,%2,%3,%4};"
                         :: "r"(sw), "r"(u0), "r"(u1), "r"(u2), "r"(u3));
        }
    };

    auto loadA = [&](int kt) {
        uint32_t sb = sbase + (uint32_t)(kt & 3) * STG_BYTES;
        const __half* A;
        size_t kstrA;
        int kb, hh;
        if (!mixed || kt < 8) {
            int k0 = (z * NST + kt) * BK;
            hh = k0 >> 8;
            A = g_X; kstrA = IDIM; kb = k0 & 255;
        } else {
            A = g_Zext; kstrA = KE; kb = (kt - 8) * BK;
            hh = 128;
        }
#pragma unroll
        for (int i = 0; i < 8; i++) {
            int t = tid + i * 256;
            int row = t >> 3, ch = t & 7;
            uint32_t sw = (uint32_t)row * 128 + ((ch ^ (row & 7)) << 4);
            cp16(sb + OFF_A + sw, A + (size_t)(m0 + row) * kstrA + kb + ch * 8);
        }
        if (tid < 32)
            cp16(sb + OFF_H + tid * 16, g_H + hh * BATCH + m0 + tid * 8);
    };

    float acc[4][8][4];
#pragma unroll
    for (int i = 0; i < 4; i++)
#pragma unroll
        for (int j = 0; j < 8; j++)
#pragma unroll
            for (int q = 0; q < 4; q++) acc[i][j][q] = 0.0f;

    const int arow_base = m_base + (lane & 15);
    const int asel = lane >> 4;
    const int brow_lane = lane & 15;          // k-row within k16 step
    const int bch_lane = (lane >> 4) & 1;     // n8 group select
    const int hrow = m_base + (lane >> 2);    // fragment-owner row

    float4 Bv[4][2];
    ldgB(0, Bv);
    loadA(0); CP_COMMIT();
    stsB(0, Bv);
    ldgB(1, Bv);
    loadA(1); CP_COMMIT();
    loadA(2); CP_COMMIT();

    for (int kt = 0; kt < NST; kt++) {
        CP_WAIT(2);
        __syncthreads();
        if (kt + 1 < NST) stsB(kt + 1, Bv);
        if (kt + 2 < NST) ldgB(kt + 2, Bv);
        if (kt + 3 < NST) loadA(kt + 3);
        CP_COMMIT();

        uint32_t sb = sbase + (uint32_t)(kt & 3) * STG_BYTES;

        // per-stage h scalars (packed to half2) for the 4 m-fragments
        uint32_t hq[4][2];
        uint32_t hbase = sb + OFF_H + (uint32_t)hrow * 2;
#pragma unroll
        for (int mf = 0; mf < 4; mf++) {
            uint32_t t0, t1;
            asm volatile("ld.shared.u16 %0, [%1];" : "=r"(t0) : "r"(hbase + mf * 32));
            asm volatile("ld.shared.u16 %0, [%1];" : "=r"(t1) : "r"(hbase + mf * 32 + 16));
            hq[mf][0] = t0 | (t0 << 16);
            hq[mf][1] = t1 | (t1 << 16);
        }

#pragma unroll
        for (int kk = 0; kk < 4; kk++) {
            uint32_t a[4][4], bt[4][4];
#pragma unroll
            for (int mf = 0; mf < 4; mf++) {
                int row = arow_base + mf * 16;
                int ch = 2 * kk + asel;
                uint32_t ad = sb + OFF_A + row * 128 + ((ch ^ (row & 7)) << 4);
                LDSM4(a[mf][0], a[mf][1], a[mf][2], a[mf][3], ad);
                HMUL2(a[mf][0], hq[mf][0]);
                HMUL2(a[mf][2], hq[mf][0]);
                HMUL2(a[mf][1], hq[mf][1]);
                HMUL2(a[mf][3], hq[mf][1]);
            }
#pragma unroll
            for (int np = 0; np < 4; np++) {
                int row = kk * 16 + brow_lane;
                int ch = (n_base >> 3) + np * 2 + bch_lane;
                uint32_t bd = sb + OFF_B + row * 256 + ((ch ^ (row & 7)) << 4);
                LDSM4T(bt[np][0], bt[np][1], bt[np][2], bt[np][3], bd);
            }
#pragma unroll
            for (int mf = 0; mf < 4; mf++)
#pragma unroll
                for (int np = 0; np < 4; np++) {
                    MMA16816(acc[mf][2 * np], a[mf], bt[np][0], bt[np][1]);
                    MMA16816(acc[mf][2 * np + 1], a[mf], bt[np][2], bt[np][3]);
                }
        }
    }
    CP_WAIT(0);

    float* dst = g_part + (size_t)z * (BATCH * ODIM);
#pragma unroll
    for (int mf = 0; mf < 4; mf++) {
#pragma unroll
        for (int nf = 0; nf < 8; nf++) {
            int m = m0 + m_base + mf * 16 + (lane >> 2);
            int o = n0 + n_base + nf * 8 + (lane & 3) * 2;
            float2 v0 = make_float2(acc[mf][nf][0], acc[mf][nf][1]);
            float2 v1 = make_float2(acc[mf][nf][2], acc[mf][nf][3]);
            *(float2*)(dst + (size_t)m * ODIM + o) = v0;
            *(float2*)(dst + (size_t)(m + 8) * ODIM + o) = v1;
        }
    }
}

// ------------------------- split-K reduction + bias --------------------------
__global__ void reduce_kernel(const float* __restrict__ base_bias,
                              const float* __restrict__ b2,
                              float* __restrict__ out) {
    int b = blockIdx.x, o = threadIdx.x;
    float acc = base_bias[o] + b2[IO + o];
#pragma unroll
    for (int s = 0; s < NSLICES; s++)
        acc += g_part[((size_t)s * BATCH + b) * ODIM + o];
    out[b * ODIM + o] = acc;
}

// ------------------------- launcher -----------------------------------------
extern "C" void kernel_launch(void* const* d_in, const int* in_sizes, int n_in,
                              void* d_out, int out_size) {
    const float* x    = (const float*)d_in[0];
    const float* cond = (const float*)d_in[1];
    const float* bw   = (const float*)d_in[2];
    const float* bb   = (const float*)d_in[3];
    const float* w1   = (const float*)d_in[4];
    const float* b1   = (const float*)d_in[5];
    const float* w2   = (const float*)d_in[6];
    const float* b2   = (const float*)d_in[7];
    float* out = (float*)d_out;

    cudaFuncSetAttribute(gemm_hmma_kernel,
                         cudaFuncAttributeMaxDynamicSharedMemorySize, SMEM_TOTAL);

    prep_kernel<<<BATCH, 256>>>(x, cond, w1, b1);
    gemm_hmma_kernel<<<dim3(ODIM / BN, BATCH / BM, NSLICES), 256, SMEM_TOTAL>>>(
        w2, bw, b2);
    reduce_kernel<<<BATCH, 256>>>(bb, b2, out);
}

// round 14
// speedup vs baseline: 1.0393x; 1.0393x over previous
#include <cuda_runtime.h>
#include <cuda_fp16.h>
#include <cstdint>

#define BATCH 512
#define IDIM 256
#define ODIM 256
#define CDIM 128
#define HDIM 128
#define IO (IDIM * ODIM)        // 65536
#define W2COLS (IO + ODIM)      // 65792
#define KTOT (HDIM * IDIM)      // 32768
#define KE 384                  // extended K: 256 (x/base) + 128 (h/biascols)
#define NSLICES 37              // 36 x 7 main BK128-units + 1 x (4 main + 3 ext)
#define BM 256
#define BN 128
#define BK 128
#define NST 7                   // stages per slice (uniform)

// ------------------------- device scratch (no allocs) -----------------------
__device__ __half g_X[(size_t)BATCH * IDIM];                // 256 KB, [b][i]
__device__ __half g_H[(size_t)129 * BATCH];                 // [hh][b]; row 128 = 1.0
__device__ __half g_W[(size_t)KTOT * ODIM];                 // 16 MB, [k][o]
__device__ __half g_Zext[(size_t)BATCH * KE];
__device__ __half g_Wext[(size_t)KE * ODIM];                // [k][o]
__device__ float g_part[(size_t)NSLICES * BATCH * ODIM];

// ------------------------- PTX helpers --------------------------------------
__device__ __forceinline__ uint32_t smem_u32(const void* p) {
    uint32_t a;
    asm("{ .reg .u64 t; cvta.to.shared.u64 t, %1; cvt.u32.u64 %0, t; }"
        : "=r"(a) : "l"(p));
    return a;
}
__device__ __forceinline__ void cp16(uint32_t s, const void* g) {
    asm volatile("cp.async.cg.shared.global [%0], [%1], 16;" :: "r"(s), "l"(g));
}
#define CP_COMMIT() asm volatile("cp.async.commit_group;" ::: "memory")
#define CP_WAIT(n)  asm volatile("cp.async.wait_group %0;" :: "n"(n) : "memory")

#define LDSM4(r0, r1, r2, r3, addr) \
    asm volatile("ldmatrix.sync.aligned.m8n8.x4.shared.b16 {%0,%1,%2,%3}, [%4];" \
        : "=r"(r0), "=r"(r1), "=r"(r2), "=r"(r3) : "r"(addr))

#define LDSM4T(r0, r1, r2, r3, addr) \
    asm volatile("ldmatrix.sync.aligned.m8n8.x4.trans.shared.b16 {%0,%1,%2,%3}, [%4];" \
        : "=r"(r0), "=r"(r1), "=r"(r2), "=r"(r3) : "r"(addr))

#define MMA16816(c, a, b0, b1) \
    asm volatile("mma.sync.aligned.m16n8k16.row.col.f32.f16.f16.f32 " \
        "{%0,%1,%2,%3}, {%4,%5,%6,%7}, {%8,%9}, {%0,%1,%2,%3};" \
        : "+f"((c)[0]), "+f"((c)[1]), "+f"((c)[2]), "+f"((c)[3]) \
        : "r"((a)[0]), "r"((a)[1]), "r"((a)[2]), "r"((a)[3]), "r"(b0), "r"(b1))

#define HMUL2(d, s) asm volatile("mul.f16x2 %0, %0, %1;" : "+r"(d) : "r"(s))

// ------------------------- fused prep kernel ---------------------------------
// blocks [0, 512):       one block per batch row: h (2 thr/output), x, Zext
// blocks [512, 1536):    W main streaming, 4 chunks/thread
// blocks [1536, 1548):   Wext streaming, 4 chunks/thread
#define ZB 512
#define WMB 1024
#define WEB 12
#define NBLK (ZB + WMB + WEB)   // 1548

__global__ void __launch_bounds__(256)
prep_all_kernel(const float* __restrict__ x,
                const float* __restrict__ cond,
                const float* __restrict__ w1,
                const float* __restrict__ b1,
                const float* __restrict__ w2,
                const float* __restrict__ baseW,
                const float* __restrict__ b2) {
    __shared__ float cs[CDIM];
    const int bid = blockIdx.x;
    const int tid = threadIdx.x;

    if (bid < ZB) {
        const int b = bid;
        if (tid < CDIM) cs[tid] = cond[b * CDIM + tid];
        __half xh = __float2half_rn(x[b * IDIM + tid]);
        g_X[b * IDIM + tid] = xh;
        g_Zext[b * KE + tid] = xh;
        __syncthreads();
        // 2 threads per h output: j = tid>>1, halves of the K range
        int j = tid >> 1, hf = tid & 1;
        int k0 = hf * 64;
        float a0 = hf ? 0.f : b1[j], a1 = 0.f, a2 = 0.f, a3 = 0.f;
#pragma unroll 4
        for (int k = k0; k < k0 + 64; k += 4) {
            a0 = fmaf(cs[k],     w1[(k)     * HDIM + j], a0);
            a1 = fmaf(cs[k + 1], w1[(k + 1) * HDIM + j], a1);
            a2 = fmaf(cs[k + 2], w1[(k + 2) * HDIM + j], a2);
            a3 = fmaf(cs[k + 3], w1[(k + 3) * HDIM + j], a3);
        }
        float s = (a0 + a1) + (a2 + a3);
        s += __shfl_xor_sync(0xffffffffu, s, 1);
        if (hf == 0) {
            __half hv = __float2half_rn(fmaxf(s, 0.0f));
            g_H[j * BATCH + b] = hv;
            g_Zext[b * KE + 256 + j] = hv;
        }
        if (tid == 255) g_H[128 * BATCH + b] = __float2half_rn(1.0f);
    } else if (bid < ZB + WMB) {
        // ---- W main: 4 chunks per thread, high MLP ----
        int u0 = (bid - ZB) * 1024 + tid;
#pragma unroll
        for (int i = 0; i < 4; i++) {
            int u = u0 + i * 256;
            int j0 = u * 8;
            int k = j0 >> 8;
            size_t in = (size_t)(k >> 8) * W2COLS + (size_t)(k & 255) * 256 + (j0 & 255);
            float4 v0 = *(const float4*)(w2 + in);
            float4 v1 = *(const float4*)(w2 + in + 4);
            union { __half e[8]; uint4 v; } o;
            o.e[0] = __float2half_rn(v0.x); o.e[1] = __float2half_rn(v0.y);
            o.e[2] = __float2half_rn(v0.z); o.e[3] = __float2half_rn(v0.w);
            o.e[4] = __float2half_rn(v1.x); o.e[5] = __float2half_rn(v1.y);
            o.e[6] = __float2half_rn(v1.z); o.e[7] = __float2half_rn(v1.w);
            ((uint4*)g_W)[u] = o.v;
        }
    } else {
        // ---- Wext: [k][o], 4 chunks per thread ----
        int u0 = (bid - ZB - WMB) * 1024 + tid;
#pragma unroll
        for (int i = 0; i < 4; i++) {
            int u = u0 + i * 256;
            int j0 = u * 8;
            int k = j0 >> 8, o0 = j0 & 255;
            float v[8];
            if (k < 256) {
                float4 a0 = *(const float4*)(baseW + k * ODIM + o0);
                float4 a1 = *(const float4*)(baseW + k * ODIM + o0 + 4);
                float4 c0 = *(const float4*)(b2 + k * ODIM + o0);
                float4 c1 = *(const float4*)(b2 + k * ODIM + o0 + 4);
                v[0]=a0.x+c0.x; v[1]=a0.y+c0.y; v[2]=a0.z+c0.z; v[3]=a0.w+c0.w;
                v[4]=a1.x+c1.x; v[5]=a1.y+c1.y; v[6]=a1.z+c1.z; v[7]=a1.w+c1.w;
            } else {
                const float* src = w2 + (size_t)(k - 256) * W2COLS + IO + o0;
                float4 a0 = *(const float4*)(src);
                float4 a1 = *(const float4*)(src + 4);
                v[0]=a0.x; v[1]=a0.y; v[2]=a0.z; v[3]=a0.w;
                v[4]=a1.x; v[5]=a1.y; v[6]=a1.z; v[7]=a1.w;
            }
            union { __half e[8]; uint4 v; } o;
#pragma unroll
            for (int j = 0; j < 8; j++) o.e[j] = __float2half_rn(v[j]);
            ((uint4*)g_Wext)[u] = o.v;
        }
    }
}

// ------------------------- HMMA GEMM (A on-the-fly, BK=128, 2-stage) --------
// C = (h∘x)@W (+ ext). BM=256 x BN=128, 256 threads (8 warps, 4m x 2n,
// warp 64x64), BK=128, double-buffered cp.async (193 KB). grid 2x2x37 = 148.
// Slice z<36: units z*7+kt. Slice 36: kt<4 -> unit 252+kt; kt>=4 -> ext kt-4.
#define STG_BYTES 98816          // A 64K + B 32K + h 512 + pad
#define OFF_A 0
#define OFF_B 65536
#define OFF_H 98304
#define SMEM_TOTAL (2 * STG_BYTES)   // 197632

__global__ void __launch_bounds__(256, 1)
gemm_hmma_kernel() {
    extern __shared__ char smem[];
    const uint32_t sbase = smem_u32(smem);
    const int tid = threadIdx.x;
    const int wid = tid >> 5, lane = tid & 31;
    const int n0 = blockIdx.x * BN;
    const int m0 = blockIdx.y * BM;
    const int z = blockIdx.z;
    const bool mixed = (z == NSLICES - 1);

    const int m_base = (wid >> 1) * 64;   // 4 warps along M
    const int n_base = (wid & 1) * 64;    // 2 warps along N

    auto load_stage = [&](int kt) {
        uint32_t sb = sbase + (uint32_t)(kt & 1) * STG_BYTES;
        const __half* A;
        const __half* B;
        size_t kstrA;
        int kb, hh;
        if (!mixed || kt < 4) {
            int k0 = (z * NST + kt) * BK;      // z=36,kt<4 -> units 252..255
            hh = k0 >> 8;
            A = g_X; kstrA = IDIM; kb = k0 & 255;
            B = g_W + (size_t)k0 * ODIM;
        } else {
            A = g_Zext; kstrA = KE; kb = (kt - 4) * BK;
            hh = 128;
            B = g_Wext + (size_t)kb * ODIM;
        }
        // A: 256 rows x 256B -> 4096 chunks, 16 per thread
#pragma unroll
        for (int i = 0; i < 16; i++) {
            int t = tid + i * 256;
            int row = t >> 4, ch = t & 15;
            uint32_t sw = (uint32_t)row * 256 + ((ch ^ (row & 7)) << 4);
            cp16(sb + OFF_A + sw, A + (size_t)(m0 + row) * kstrA + kb + ch * 8);
        }
        // B: 128 k-rows x 256B -> 2048 chunks, 8 per thread
#pragma unroll
        for (int i = 0; i < 8; i++) {
            int t = tid + i * 256;
            int row = t >> 4, ch = t & 15;
            uint32_t sw = (uint32_t)row * 256 + ((ch ^ (row & 7)) << 4);
            cp16(sb + OFF_B + sw, B + (size_t)row * ODIM + n0 + ch * 8);
        }
        // h column for this stage's hh: 256 rows x 2B = 512B
        if (tid < 32)
            cp16(sb + OFF_H + tid * 16, g_H + hh * BATCH + m0 + tid * 8);
    };

    float acc[4][8][4];
#pragma unroll
    for (int i = 0; i < 4; i++)
#pragma unroll
        for (int j = 0; j < 8; j++)
#pragma unroll
            for (int q = 0; q < 4; q++) acc[i][j][q] = 0.0f;

    const int arow_base = m_base + (lane & 15);
    const int asel = lane >> 4;
    const int brow_lane = lane & 15;          // k-row within k16 step
    const int bch_lane = (lane >> 4) & 1;     // n8 group select
    const int hrow = m_base + (lane >> 2);    // fragment-owner row

    load_stage(0); CP_COMMIT();

    for (int kt = 0; kt < NST; kt++) {
        CP_WAIT(0);            // stage kt fully arrived
        __syncthreads();       // all warps done reading the other buffer
        if (kt + 1 < NST) { load_stage(kt + 1); CP_COMMIT(); }

        uint32_t sb = sbase + (uint32_t)(kt & 1) * STG_BYTES;

        // per-stage h scalars (packed to half2) for the 4 m-fragments
        uint32_t hq[4][2];
        uint32_t hbase = sb + OFF_H + (uint32_t)hrow * 2;
#pragma unroll
        for (int mf = 0; mf < 4; mf++) {
            uint32_t t0, t1;
            asm volatile("ld.shared.u16 %0, [%1];" : "=r"(t0) : "r"(hbase + mf * 32));
            asm volatile("ld.shared.u16 %0, [%1];" : "=r"(t1) : "r"(hbase + mf * 32 + 16));
            hq[mf][0] = t0 | (t0 << 16);
            hq[mf][1] = t1 | (t1 << 16);
        }

#pragma unroll
        for (int kk = 0; kk < 8; kk++) {
            uint32_t a[4][4], bt[4][4];
#pragma unroll
            for (int mf = 0; mf < 4; mf++) {
                int row = arow_base + mf * 16;
                int ch = 2 * kk + asel;
                uint32_t ad = sb + OFF_A + row * 256 + ((ch ^ (row & 7)) << 4);
                LDSM4(a[mf][0], a[mf][1], a[mf][2], a[mf][3], ad);
                HMUL2(a[mf][0], hq[mf][0]);
                HMUL2(a[mf][2], hq[mf][0]);
                HMUL2(a[mf][1], hq[mf][1]);
                HMUL2(a[mf][3], hq[mf][1]);
            }
#pragma unroll
            for (int np = 0; np < 4; np++) {
                int row = kk * 16 + brow_lane;
                int ch = (n_base >> 3) + np * 2 + bch_lane;
                uint32_t bd = sb + OFF_B + row * 256 + ((ch ^ (row & 7)) << 4);
                LDSM4T(bt[np][0], bt[np][1], bt[np][2], bt[np][3], bd);
            }
#pragma unroll
            for (int mf = 0; mf < 4; mf++)
#pragma unroll
                for (int np = 0; np < 4; np++) {
                    MMA16816(acc[mf][2 * np], a[mf], bt[np][0], bt[np][1]);
                    MMA16816(acc[mf][2 * np + 1], a[mf], bt[np][2], bt[np][3]);
                }
        }
    }
    CP_WAIT(0);

    float* dst = g_part + (size_t)z * (BATCH * ODIM);
#pragma unroll
    for (int mf = 0; mf < 4; mf++) {
#pragma unroll
        for (int nf = 0; nf < 8; nf++) {
            int m = m0 + m_base + mf * 16 + (lane >> 2);
            int o = n0 + n_base + nf * 8 + (lane & 3) * 2;
            float2 v0 = make_float2(acc[mf][nf][0], acc[mf][nf][1]);
            float2 v1 = make_float2(acc[mf][nf][2], acc[mf][nf][3]);
            *(float2*)(dst + (size_t)m * ODIM + o) = v0;
            *(float2*)(dst + (size_t)(m + 8) * ODIM + o) = v1;
        }
    }
}

// ------------------------- split-K reduction + bias --------------------------
__global__ void reduce_kernel(const float* __restrict__ base_bias,
                              const float* __restrict__ b2,
                              float* __restrict__ out) {
    int b = blockIdx.x, o = threadIdx.x;
    float acc = base_bias[o] + b2[IO + o];
#pragma unroll
    for (int s = 0; s < NSLICES; s++)
        acc += g_part[((size_t)s * BATCH + b) * ODIM + o];
    out[b * ODIM + o] = acc;
}

// ------------------------- launcher -----------------------------------------
extern "C" void kernel_launch(void* const* d_in, const int* in_sizes, int n_in,
                              void* d_out, int out_size) {
    const float* x    = (const float*)d_in[0];
    const float* cond = (const float*)d_in[1];
    const float* bw   = (const float*)d_in[2];
    const float* bb   = (const float*)d_in[3];
    const float* w1   = (const float*)d_in[4];
    const float* b1   = (const float*)d_in[5];
    const float* w2   = (const float*)d_in[6];
    const float* b2   = (const float*)d_in[7];
    float* out = (float*)d_out;

    cudaFuncSetAttribute(gemm_hmma_kernel,
                         cudaFuncAttributeMaxDynamicSharedMemorySize, SMEM_TOTAL);

    prep_all_kernel<<<NBLK, 256>>>(x, cond, w1, b1, w2, bw, b2);
    gemm_hmma_kernel<<<dim3(ODIM / BN, BATCH / BM, NSLICES), 256, SMEM_TOTAL>>>();
    reduce_kernel<<<BATCH, 256>>>(bb, b2, out);
}